// round 6
// baseline (speedup 1.0000x reference)
#include <cuda_runtime.h>
#include <cuda_bf16.h>
#include <math.h>
#include <stdint.h>

// Problem constants
#define T_TOK 4096
#define H_DIM 2048
#define E_NUM 8
#define I_DIM 768
#define KSEL  2
#define N1    (2*I_DIM)
#define ROWS_TOTAL (T_TOK*KSEL)
#define AUX_COEF 0.001f

// ---------------- scratch (device-code access ONLY — never host args) -------
__device__ uint4 g_x_hi4[(size_t)T_TOK * H_DIM / 8];
__device__ uint4 g_x_lo4[(size_t)T_TOK * H_DIM / 8];
__device__ uint4 g_w1_hi4[(size_t)E_NUM * N1 * H_DIM / 8];
__device__ uint4 g_w1_lo4[(size_t)E_NUM * N1 * H_DIM / 8];
__device__ uint4 g_w2_hi4[(size_t)E_NUM * H_DIM * I_DIM / 8];
__device__ uint4 g_w2_lo4[(size_t)E_NUM * H_DIM * I_DIM / 8];
__device__ uint4 g_i_hi4[(size_t)ROWS_TOTAL * I_DIM / 8];
__device__ uint4 g_i_lo4[(size_t)ROWS_TOTAL * I_DIM / 8];
__device__ float g_y[(size_t)ROWS_TOTAL * H_DIM];
__device__ int   g_sel[ROWS_TOTAL];
__device__ float g_wt[ROWS_TOTAL];
__device__ int   g_counts[E_NUM];
__device__ int   g_ofs[E_NUM];
__device__ int   g_cursor[E_NUM];
__device__ int   g_rows_tok[ROWS_TOTAL];
__device__ int   g_rows_slot[ROWS_TOTAL];
__device__ float g_rows_w[ROWS_TOTAL];
__device__ float g_prob_sum[E_NUM];

// ---------------- helpers ----------------
__device__ __forceinline__ uint32_t smem_u32(const void* p) {
    uint32_t a;
    asm("{ .reg .u64 t; cvta.to.shared.u64 t, %1; cvt.u32.u64 %0, t; }" : "=r"(a) : "l"(p));
    return a;
}
__device__ __forceinline__ void ldsm_x4(uint32_t* r, uint32_t addr) {
    asm volatile("ldmatrix.sync.aligned.m8n8.x4.shared.b16 {%0,%1,%2,%3}, [%4];"
        : "=r"(r[0]), "=r"(r[1]), "=r"(r[2]), "=r"(r[3]) : "r"(addr));
}
__device__ __forceinline__ void mma16816(float* c, const uint32_t* a, const uint32_t* b) {
    asm volatile("mma.sync.aligned.m16n8k16.row.col.f32.bf16.bf16.f32 "
        "{%0,%1,%2,%3}, {%4,%5,%6,%7}, {%8,%9}, {%0,%1,%2,%3};"
        : "+f"(c[0]), "+f"(c[1]), "+f"(c[2]), "+f"(c[3])
        : "r"(a[0]), "r"(a[1]), "r"(a[2]), "r"(a[3]), "r"(b[0]), "r"(b[1]));
}
__device__ __forceinline__ void split4(float4 v, uint2& h, uint2& l) {
    __nv_bfloat162 hxy = __floats2bfloat162_rn(v.x, v.y);
    __nv_bfloat162 hzw = __floats2bfloat162_rn(v.z, v.w);
    float2 fxy = __bfloat1622float2(hxy);
    float2 fzw = __bfloat1622float2(hzw);
    __nv_bfloat162 lxy = __floats2bfloat162_rn(v.x - fxy.x, v.y - fxy.y);
    __nv_bfloat162 lzw = __floats2bfloat162_rn(v.z - fzw.x, v.w - fzw.y);
    h.x = *reinterpret_cast<uint32_t*>(&hxy); h.y = *reinterpret_cast<uint32_t*>(&hzw);
    l.x = *reinterpret_cast<uint32_t*>(&lxy); l.y = *reinterpret_cast<uint32_t*>(&lzw);
}

// ---------------- split precompute (globals selected in DEVICE code) --------
__global__ void split_kernel(const float4* __restrict__ in, int which, int n4) {
    int i = blockIdx.x * blockDim.x + threadIdx.x;
    if (i >= n4) return;
    uint2* hi; uint2* lo;
    if (which == 0)      { hi = (uint2*)g_x_hi4;  lo = (uint2*)g_x_lo4;  }
    else if (which == 1) { hi = (uint2*)g_w1_hi4; lo = (uint2*)g_w1_lo4; }
    else                 { hi = (uint2*)g_w2_hi4; lo = (uint2*)g_w2_lo4; }
    uint2 h, l;
    split4(in[i], h, l);
    hi[i] = h; lo[i] = l;
}

// ---------------- init / router / offsets / scatter (validated R1/R3) ------
__global__ void init_kernel() {
    int i = threadIdx.x;
    if (i < E_NUM) { g_counts[i] = 0; g_prob_sum[i] = 0.f; }
}

__global__ void router_kernel(const float* __restrict__ x,
                              const float* __restrict__ gw,
                              float* __restrict__ logits_out) {
    const int t = blockIdx.x;
    const float* xr = x + (size_t)t * H_DIM;
    float acc[E_NUM];
#pragma unroll
    for (int e = 0; e < E_NUM; e++) acc[e] = 0.f;
    for (int h = threadIdx.x; h < H_DIM; h += blockDim.x) {
        float xv = xr[h];
        const float4 g0 = *(const float4*)(gw + (size_t)h * E_NUM);
        const float4 g1 = *(const float4*)(gw + (size_t)h * E_NUM + 4);
        acc[0] += xv * g0.x; acc[1] += xv * g0.y; acc[2] += xv * g0.z; acc[3] += xv * g0.w;
        acc[4] += xv * g1.x; acc[5] += xv * g1.y; acc[6] += xv * g1.z; acc[7] += xv * g1.w;
    }
#pragma unroll
    for (int e = 0; e < E_NUM; e++)
#pragma unroll
        for (int o = 16; o; o >>= 1) acc[e] += __shfl_xor_sync(0xffffffffu, acc[e], o);
    __shared__ float red[E_NUM][8];
    int warp = threadIdx.x >> 5, lane = threadIdx.x & 31;
    if (lane == 0)
#pragma unroll
        for (int e = 0; e < E_NUM; e++) red[e][warp] = acc[e];
    __syncthreads();
    if (threadIdx.x == 0) {
        float lg[E_NUM];
#pragma unroll
        for (int e = 0; e < E_NUM; e++) {
            float s = 0.f;
#pragma unroll
            for (int w = 0; w < 8; w++) s += red[e][w];
            lg[e] = s;
        }
        if (logits_out)
#pragma unroll
            for (int e = 0; e < E_NUM; e++) logits_out[(size_t)t * E_NUM + e] = lg[e];
        float mx = lg[0];
#pragma unroll
        for (int e = 1; e < E_NUM; e++) mx = fmaxf(mx, lg[e]);
        float p[E_NUM], s = 0.f;
#pragma unroll
        for (int e = 0; e < E_NUM; e++) { p[e] = expf(lg[e] - mx); s += p[e]; }
        float inv = 1.f / s;
#pragma unroll
        for (int e = 0; e < E_NUM; e++) { p[e] *= inv; atomicAdd(&g_prob_sum[e], p[e]); }
        bool used[E_NUM];
#pragma unroll
        for (int e = 0; e < E_NUM; e++) used[e] = false;
        int si[KSEL]; float sp[KSEL]; float wsum = 0.f;
#pragma unroll
        for (int k = 0; k < KSEL; k++) {
            int bi = -1; float bv = -1.f;
#pragma unroll
            for (int e = 0; e < E_NUM; e++)
                if (!used[e] && p[e] > bv) { bv = p[e]; bi = e; }
            used[bi] = true; si[k] = bi; sp[k] = bv; wsum += bv;
        }
        float winv = 1.f / wsum;
#pragma unroll
        for (int k = 0; k < KSEL; k++) {
            g_sel[t * KSEL + k] = si[k];
            g_wt[t * KSEL + k]  = sp[k] * winv;
            atomicAdd(&g_counts[si[k]], 1);
        }
    }
}

__global__ void offsets_kernel() {
    if (threadIdx.x == 0) {
        int run = 0;
        for (int e = 0; e < E_NUM; e++) { g_ofs[e] = run; g_cursor[e] = run; run += g_counts[e]; }
    }
}

__global__ void scatter_kernel() {
    int i = blockIdx.x * blockDim.x + threadIdx.x;
    if (i >= ROWS_TOTAL) return;
    int e = g_sel[i];
    int p = atomicAdd(&g_cursor[e], 1);
    g_rows_tok[p]  = i / KSEL;
    g_rows_slot[p] = i % KSEL;
    g_rows_w[p]    = g_wt[i];
}

// ---------------- HMMA expert GEMM (R3 structure, pre-split inputs) ---------
// CTA tile 128x128, K-chunk 32, 2-stage LDG->reg->STS double buffer (proven).
// smem arrays stride 40 bf16 (80B rows), only first 64B of each row used.
#define SROW 40
#define ARR_BYTES (128 * SROW * 2)     // 10240
#define STG_BYTES (4 * ARR_BYTES)      // 40960
#define OFF_AHI 0
#define OFF_ALO ARR_BYTES
#define OFF_BHI (2 * ARR_BYTES)
#define OFF_BLO (3 * ARR_BYTES)
#define SMEM_TOT (2 * STG_BYTES)       // 81920

template<int KDIM, int MODE>
__global__ void __launch_bounds__(256)
moe_gemm_mma() {
    constexpr int NCH  = KDIM / 32;
    constexpr int NDIM = (MODE == 1) ? N1 : H_DIM;
    // Globals bound in DEVICE code (the R4/R5 failure was host-side symbol args)
    const __nv_bfloat16* a_hi = (MODE == 1) ? (const __nv_bfloat16*)g_x_hi4 : (const __nv_bfloat16*)g_i_hi4;
    const __nv_bfloat16* a_lo = (MODE == 1) ? (const __nv_bfloat16*)g_x_lo4 : (const __nv_bfloat16*)g_i_lo4;
    const __nv_bfloat16* b_hi = (MODE == 1) ? (const __nv_bfloat16*)g_w1_hi4 : (const __nv_bfloat16*)g_w2_hi4;
    const __nv_bfloat16* b_lo = (MODE == 1) ? (const __nv_bfloat16*)g_w1_lo4 : (const __nv_bfloat16*)g_w2_lo4;

    const int e   = blockIdx.z;
    const int cnt = g_counts[e];
    const int m0  = blockIdx.x * 128;
    if (m0 >= cnt) return;
    const int nb  = blockIdx.y;
    const int ofs = g_ofs[e];

    extern __shared__ char smem[];
    const uint32_t sb = smem_u32(smem);

    const int tid  = threadIdx.x;
    const int wid  = tid >> 5;
    const int lane = tid & 31;
    const int wm   = wid & 1;
    const int wn   = wid >> 1;

    // ---- loader: i in {0,1}; per thread 2 row-chunks of 16B per array ----
    const __nv_bfloat16* aH[2]; const __nv_bfloat16* aL[2];
    const __nv_bfloat16* bH[2]; const __nv_bfloat16* bL[2];
    uint32_t soff[2];
#pragma unroll
    for (int i = 0; i < 2; i++) {
        int ei = i * 256 + tid;
        int r = ei >> 2, q = ei & 3;               // r: 0..127, q: 16B chunk
        soff[i] = (uint32_t)(r * SROW * 2 + q * 16);
        int lm = m0 + r; if (lm > cnt - 1) lm = cnt - 1;
        size_t arow;
        if (MODE == 1) arow = (size_t)__ldg(&g_rows_tok[ofs + lm]) * H_DIM;
        else           arow = (size_t)(ofs + lm) * I_DIM;
        aH[i] = a_hi + arow + q * 8;
        aL[i] = a_lo + arow + q * 8;
        int gn;
        if (MODE == 1) gn = (r < 64) ? (nb * 64 + r) : (I_DIM + nb * 64 + (r - 64));
        else           gn = nb * 128 + r;
        size_t brow = ((size_t)e * NDIM + gn) * KDIM;
        bH[i] = b_hi + brow + q * 8;
        bL[i] = b_lo + brow + q * 8;
    }

    uint4 vAH[2], vAL[2], vBH[2], vBL[2];
    auto load_chunk = [&](int c) {
        const int kt = c * 32;
#pragma unroll
        for (int i = 0; i < 2; i++) {
            vAH[i] = __ldg((const uint4*)(aH[i] + kt));
            vAL[i] = __ldg((const uint4*)(aL[i] + kt));
            vBH[i] = __ldg((const uint4*)(bH[i] + kt));
            vBL[i] = __ldg((const uint4*)(bL[i] + kt));
        }
    };
    auto sts_chunk = [&](int s) {
        char* st = smem + s * STG_BYTES;
#pragma unroll
        for (int i = 0; i < 2; i++) {
            *(uint4*)(st + OFF_AHI + soff[i]) = vAH[i];
            *(uint4*)(st + OFF_ALO + soff[i]) = vAL[i];
            *(uint4*)(st + OFF_BHI + soff[i]) = vBH[i];
            *(uint4*)(st + OFF_BLO + soff[i]) = vBL[i];
        }
    };

    // ldmatrix per-thread base byte offsets within an array (R3-proven)
    const uint32_t a_base = ((wm * 64 + (lane & 15)) * SROW + (lane >> 4) * 8) * 2;
    const uint32_t b_base = ((wn * 32 + ((lane >> 4) << 3) + (lane & 7)) * SROW + ((lane >> 3) & 1) * 8) * 2;

    float acc[4][4][4];
#pragma unroll
    for (int i = 0; i < 4; i++)
#pragma unroll
        for (int j = 0; j < 4; j++)
#pragma unroll
            for (int k = 0; k < 4; k++) acc[i][j][k] = 0.f;

    load_chunk(0);
    sts_chunk(0);
    __syncthreads();

    for (int c = 0; c < NCH; c++) {
        const int s = c & 1;
        if (c + 1 < NCH) load_chunk(c + 1);

        const uint32_t stg = sb + s * STG_BYTES;
#pragma unroll
        for (int kk = 0; kk < 2; kk++) {
            const uint32_t koff = kk * 32;     // 16 bf16 = 32 B
            uint32_t af[4][4], bh2[2][4], bl2[2][4];
#pragma unroll
            for (int im = 0; im < 4; im++)
                ldsm_x4(af[im], stg + OFF_AHI + a_base + im * (16 * SROW * 2) + koff);
#pragma unroll
            for (int g = 0; g < 2; g++) {
                ldsm_x4(bh2[g], stg + OFF_BHI + b_base + g * (16 * SROW * 2) + koff);
                ldsm_x4(bl2[g], stg + OFF_BLO + b_base + g * (16 * SROW * 2) + koff);
            }
#pragma unroll
            for (int im = 0; im < 4; im++)
#pragma unroll
                for (int g = 0; g < 2; g++) {
                    mma16816(acc[im][g * 2 + 0], af[im], &bh2[g][0]);
                    mma16816(acc[im][g * 2 + 1], af[im], &bh2[g][2]);
                    mma16816(acc[im][g * 2 + 0], af[im], &bl2[g][0]);
                    mma16816(acc[im][g * 2 + 1], af[im], &bl2[g][2]);
                }
#pragma unroll
            for (int im = 0; im < 4; im++)
                ldsm_x4(af[im], stg + OFF_ALO + a_base + im * (16 * SROW * 2) + koff);
#pragma unroll
            for (int im = 0; im < 4; im++)
#pragma unroll
                for (int g = 0; g < 2; g++) {
                    mma16816(acc[im][g * 2 + 0], af[im], &bh2[g][0]);
                    mma16816(acc[im][g * 2 + 1], af[im], &bh2[g][2]);
                }
        }
        __syncthreads();
        if (c + 1 < NCH) {
            sts_chunk(s ^ 1);
            __syncthreads();
        }
    }

    // ---------------- epilogue ----------------
    if (MODE == 1) {
        float* Cs = (float*)smem;   // 64 KB, aliases stages (all reads done)
#pragma unroll
        for (int im = 0; im < 4; im++)
#pragma unroll
            for (int jn = 0; jn < 4; jn++) {
                int row = wm * 64 + im * 16 + (lane >> 2);
                int col = wn * 32 + jn * 8 + (lane & 3) * 2;
                *(float2*)&Cs[row * 128 + col]       = make_float2(acc[im][jn][0], acc[im][jn][1]);
                *(float2*)&Cs[(row + 8) * 128 + col] = make_float2(acc[im][jn][2], acc[im][jn][3]);
            }
        __syncthreads();
        int r = tid >> 1, half = tid & 1;
        if (m0 + r < cnt) {
            int grow = ofs + m0 + r;
            uint32_t hi16[16], lo16[16];
#pragma unroll
            for (int j = 0; j < 16; j++) {
                float g0 = Cs[r * 128 + half * 32 + 2 * j];
                float u0 = Cs[r * 128 + 64 + half * 32 + 2 * j];
                float g1 = Cs[r * 128 + half * 32 + 2 * j + 1];
                float u1 = Cs[r * 128 + 64 + half * 32 + 2 * j + 1];
                float v0 = (g0 / (1.f + __expf(-g0))) * u0;
                float v1 = (g1 / (1.f + __expf(-g1))) * u1;
                __nv_bfloat162 hh = __floats2bfloat162_rn(v0, v1);
                float2 hf = __bfloat1622float2(hh);
                __nv_bfloat162 ll = __floats2bfloat162_rn(v0 - hf.x, v1 - hf.y);
                hi16[j] = *reinterpret_cast<uint32_t*>(&hh);
                lo16[j] = *reinterpret_cast<uint32_t*>(&ll);
            }
            size_t off = ((size_t)grow * I_DIM + nb * 64 + half * 32) / 8;
#pragma unroll
            for (int j = 0; j < 4; j++) {
                g_i_hi4[off + j] = ((uint4*)hi16)[j];
                g_i_lo4[off + j] = ((uint4*)lo16)[j];
            }
        }
    } else {
#pragma unroll
        for (int im = 0; im < 4; im++) {
#pragma unroll
            for (int half = 0; half < 2; half++) {
                int r = m0 + wm * 64 + im * 16 + (lane >> 2) + half * 8;
                if (r < cnt) {
                    int gr = ofs + r;
                    float wgt = g_rows_w[gr];
                    int t = g_rows_tok[gr], sl = g_rows_slot[gr];
                    float* base = g_y + ((size_t)t * KSEL + sl) * H_DIM + nb * 128 + wn * 32;
#pragma unroll
                    for (int jn = 0; jn < 4; jn++) {
                        int col = jn * 8 + (lane & 3) * 2;
                        float2 v = make_float2(acc[im][jn][half * 2] * wgt,
                                               acc[im][jn][half * 2 + 1] * wgt);
                        *(float2*)(base + col) = v;
                    }
                }
            }
        }
    }
}

// ---------------- combine / aux ----------------
__global__ void combine_kernel(float* __restrict__ out) {
    int i = blockIdx.x * blockDim.x + threadIdx.x;
    if (i >= T_TOK * H_DIM / 4) return;
    const int nv = H_DIM / 4;
    int t = i / nv, n = i - t * nv;
    const float4* y = (const float4*)g_y;
    float4 a = y[((size_t)t * KSEL + 0) * nv + n];
    float4 b = y[((size_t)t * KSEL + 1) * nv + n];
    a.x += b.x; a.y += b.y; a.z += b.z; a.w += b.w;
    ((float4*)out)[i] = a;
}

__global__ void aux_kernel(float* __restrict__ aux_out) {
    if (threadIdx.x == 0) {
        float aux = 0.f;
        float invT = 1.f / (float)T_TOK;
        for (int e = 0; e < E_NUM; e++)
            aux += (g_prob_sum[e] * invT) * ((float)g_counts[e] * invT);
        aux_out[0] = aux * (float)E_NUM * AUX_COEF;
    }
}

// ---------------- launch ----------------
extern "C" void kernel_launch(void* const* d_in, const int* in_sizes, int n_in,
                              void* d_out, int out_size) {
    const float* x   = (const float*)d_in[0];
    const float* gw  = (const float*)d_in[1];
    const float* gup = (const float*)d_in[2];
    const float* dwn = (const float*)d_in[3];
    float* out = (float*)d_out;

    const long long need_logits = (long long)T_TOK * H_DIM + (long long)T_TOK * E_NUM;
    float* logits = ((long long)out_size >= need_logits) ? out + (size_t)T_TOK * H_DIM : nullptr;
    float* auxp   = ((long long)out_size >= need_logits + 1) ? logits + (size_t)T_TOK * E_NUM : nullptr;

    cudaFuncSetAttribute(moe_gemm_mma<H_DIM, 1>, cudaFuncAttributeMaxDynamicSharedMemorySize, SMEM_TOT);
    cudaFuncSetAttribute(moe_gemm_mma<I_DIM, 2>, cudaFuncAttributeMaxDynamicSharedMemorySize, SMEM_TOT);

    init_kernel<<<1, 32>>>();
    router_kernel<<<T_TOK, 256>>>(x, gw, logits);
    offsets_kernel<<<1, 32>>>();
    scatter_kernel<<<(ROWS_TOTAL + 255) / 256, 256>>>();

    // Pre-split fp32 -> bf16 hi/lo (x, gate_up, down); outputs selected in device code
    {
        int n4 = T_TOK * H_DIM / 4;
        split_kernel<<<(n4 + 255) / 256, 256>>>((const float4*)x, 0, n4);
        n4 = E_NUM * N1 * H_DIM / 4;
        split_kernel<<<(n4 + 255) / 256, 256>>>((const float4*)gup, 1, n4);
        n4 = E_NUM * H_DIM * I_DIM / 4;
        split_kernel<<<(n4 + 255) / 256, 256>>>((const float4*)dwn, 2, n4);
    }

    // GEMM1: (gathered x) @ gate_up^T, fused silu -> g_i_hi/g_i_lo
    moe_gemm_mma<H_DIM, 1><<<dim3(32, I_DIM / 64, E_NUM), 256, SMEM_TOT>>>();
    // GEMM2: inter @ down^T, scaled, scattered -> g_y
    moe_gemm_mma<I_DIM, 2><<<dim3(32, H_DIM / 128, E_NUM), 256, SMEM_TOT>>>();

    combine_kernel<<<(T_TOK * H_DIM / 4 + 255) / 256, 256>>>(out);
    if (auxp) aux_kernel<<<1, 32>>>(auxp);
}

// round 7
// speedup vs baseline: 1.1126x; 1.1126x over previous
#include <cuda_runtime.h>
#include <cuda_bf16.h>
#include <math.h>
#include <stdint.h>

// Problem constants
#define T_TOK 4096
#define H_DIM 2048
#define E_NUM 8
#define I_DIM 768
#define KSEL  2
#define N1    (2*I_DIM)
#define ROWS_TOTAL (T_TOK*KSEL)
#define AUX_COEF 0.001f

// ---------------- scratch (device-code access ONLY — never host args) -------
__device__ uint4 g_x_hi4[(size_t)T_TOK * H_DIM / 8];
__device__ uint4 g_x_lo4[(size_t)T_TOK * H_DIM / 8];
__device__ uint4 g_w1_hi4[(size_t)E_NUM * N1 * H_DIM / 8];
__device__ uint4 g_w1_lo4[(size_t)E_NUM * N1 * H_DIM / 8];
__device__ uint4 g_w2_hi4[(size_t)E_NUM * H_DIM * I_DIM / 8];
__device__ uint4 g_w2_lo4[(size_t)E_NUM * H_DIM * I_DIM / 8];
__device__ uint4 g_i_hi4[(size_t)ROWS_TOTAL * I_DIM / 8];
__device__ uint4 g_i_lo4[(size_t)ROWS_TOTAL * I_DIM / 8];
__device__ float g_y[(size_t)ROWS_TOTAL * H_DIM];
__device__ int   g_sel[ROWS_TOTAL];
__device__ float g_wt[ROWS_TOTAL];
__device__ int   g_counts[E_NUM];
__device__ int   g_ofs[E_NUM];
__device__ int   g_cursor[E_NUM];
__device__ int   g_rows_tok[ROWS_TOTAL];
__device__ int   g_rows_slot[ROWS_TOTAL];
__device__ float g_rows_w[ROWS_TOTAL];
__device__ float g_prob_sum[E_NUM];

// ---------------- helpers ----------------
__device__ __forceinline__ uint32_t smem_u32(const void* p) {
    uint32_t a;
    asm("{ .reg .u64 t; cvta.to.shared.u64 t, %1; cvt.u32.u64 %0, t; }" : "=r"(a) : "l"(p));
    return a;
}
__device__ __forceinline__ void ldsm_x4(uint32_t* r, uint32_t addr) {
    asm volatile("ldmatrix.sync.aligned.m8n8.x4.shared.b16 {%0,%1,%2,%3}, [%4];"
        : "=r"(r[0]), "=r"(r[1]), "=r"(r[2]), "=r"(r[3]) : "r"(addr));
}
__device__ __forceinline__ void mma16816(float* c, const uint32_t* a, const uint32_t* b) {
    asm volatile("mma.sync.aligned.m16n8k16.row.col.f32.bf16.bf16.f32 "
        "{%0,%1,%2,%3}, {%4,%5,%6,%7}, {%8,%9}, {%0,%1,%2,%3};"
        : "+f"(c[0]), "+f"(c[1]), "+f"(c[2]), "+f"(c[3])
        : "r"(a[0]), "r"(a[1]), "r"(a[2]), "r"(a[3]), "r"(b[0]), "r"(b[1]));
}
__device__ __forceinline__ void cpa16(uint32_t dst, const void* src) {
    asm volatile("cp.async.cg.shared.global [%0], [%1], 16;" :: "r"(dst), "l"(src) : "memory");
}
#define CP_COMMIT() asm volatile("cp.async.commit_group;" ::: "memory")
#define CP_WAIT2()  asm volatile("cp.async.wait_group 2;" ::: "memory")

__device__ __forceinline__ void split4(float4 v, uint2& h, uint2& l) {
    __nv_bfloat162 hxy = __floats2bfloat162_rn(v.x, v.y);
    __nv_bfloat162 hzw = __floats2bfloat162_rn(v.z, v.w);
    float2 fxy = __bfloat1622float2(hxy);
    float2 fzw = __bfloat1622float2(hzw);
    __nv_bfloat162 lxy = __floats2bfloat162_rn(v.x - fxy.x, v.y - fxy.y);
    __nv_bfloat162 lzw = __floats2bfloat162_rn(v.z - fzw.x, v.w - fzw.y);
    h.x = *reinterpret_cast<uint32_t*>(&hxy); h.y = *reinterpret_cast<uint32_t*>(&hzw);
    l.x = *reinterpret_cast<uint32_t*>(&lxy); l.y = *reinterpret_cast<uint32_t*>(&lzw);
}

// ---------------- split precompute (globals selected in DEVICE code) --------
__global__ void split_kernel(const float4* __restrict__ in, int which, int n4) {
    int i = blockIdx.x * blockDim.x + threadIdx.x;
    if (i >= n4) return;
    uint2* hi; uint2* lo;
    if (which == 0)      { hi = (uint2*)g_x_hi4;  lo = (uint2*)g_x_lo4;  }
    else if (which == 1) { hi = (uint2*)g_w1_hi4; lo = (uint2*)g_w1_lo4; }
    else                 { hi = (uint2*)g_w2_hi4; lo = (uint2*)g_w2_lo4; }
    uint2 h, l;
    split4(in[i], h, l);
    hi[i] = h; lo[i] = l;
}

// ---------------- init / router / offsets / scatter (validated) ------------
__global__ void init_kernel() {
    int i = threadIdx.x;
    if (i < E_NUM) { g_counts[i] = 0; g_prob_sum[i] = 0.f; }
}

__global__ void router_kernel(const float* __restrict__ x,
                              const float* __restrict__ gw,
                              float* __restrict__ logits_out) {
    const int t = blockIdx.x;
    const float* xr = x + (size_t)t * H_DIM;
    float acc[E_NUM];
#pragma unroll
    for (int e = 0; e < E_NUM; e++) acc[e] = 0.f;
    for (int h = threadIdx.x; h < H_DIM; h += blockDim.x) {
        float xv = xr[h];
        const float4 g0 = *(const float4*)(gw + (size_t)h * E_NUM);
        const float4 g1 = *(const float4*)(gw + (size_t)h * E_NUM + 4);
        acc[0] += xv * g0.x; acc[1] += xv * g0.y; acc[2] += xv * g0.z; acc[3] += xv * g0.w;
        acc[4] += xv * g1.x; acc[5] += xv * g1.y; acc[6] += xv * g1.z; acc[7] += xv * g1.w;
    }
#pragma unroll
    for (int e = 0; e < E_NUM; e++)
#pragma unroll
        for (int o = 16; o; o >>= 1) acc[e] += __shfl_xor_sync(0xffffffffu, acc[e], o);
    __shared__ float red[E_NUM][8];
    int warp = threadIdx.x >> 5, lane = threadIdx.x & 31;
    if (lane == 0)
#pragma unroll
        for (int e = 0; e < E_NUM; e++) red[e][warp] = acc[e];
    __syncthreads();
    if (threadIdx.x == 0) {
        float lg[E_NUM];
#pragma unroll
        for (int e = 0; e < E_NUM; e++) {
            float s = 0.f;
#pragma unroll
            for (int w = 0; w < 8; w++) s += red[e][w];
            lg[e] = s;
        }
        if (logits_out)
#pragma unroll
            for (int e = 0; e < E_NUM; e++) logits_out[(size_t)t * E_NUM + e] = lg[e];
        float mx = lg[0];
#pragma unroll
        for (int e = 1; e < E_NUM; e++) mx = fmaxf(mx, lg[e]);
        float p[E_NUM], s = 0.f;
#pragma unroll
        for (int e = 0; e < E_NUM; e++) { p[e] = expf(lg[e] - mx); s += p[e]; }
        float inv = 1.f / s;
#pragma unroll
        for (int e = 0; e < E_NUM; e++) { p[e] *= inv; atomicAdd(&g_prob_sum[e], p[e]); }
        bool used[E_NUM];
#pragma unroll
        for (int e = 0; e < E_NUM; e++) used[e] = false;
        int si[KSEL]; float sp[KSEL]; float wsum = 0.f;
#pragma unroll
        for (int k = 0; k < KSEL; k++) {
            int bi = -1; float bv = -1.f;
#pragma unroll
            for (int e = 0; e < E_NUM; e++)
                if (!used[e] && p[e] > bv) { bv = p[e]; bi = e; }
            used[bi] = true; si[k] = bi; sp[k] = bv; wsum += bv;
        }
        float winv = 1.f / wsum;
#pragma unroll
        for (int k = 0; k < KSEL; k++) {
            g_sel[t * KSEL + k] = si[k];
            g_wt[t * KSEL + k]  = sp[k] * winv;
            atomicAdd(&g_counts[si[k]], 1);
        }
    }
}

__global__ void offsets_kernel() {
    if (threadIdx.x == 0) {
        int run = 0;
        for (int e = 0; e < E_NUM; e++) { g_ofs[e] = run; g_cursor[e] = run; run += g_counts[e]; }
    }
}

__global__ void scatter_kernel() {
    int i = blockIdx.x * blockDim.x + threadIdx.x;
    if (i >= ROWS_TOTAL) return;
    int e = g_sel[i];
    int p = atomicAdd(&g_cursor[e], 1);
    g_rows_tok[p]  = i / KSEL;
    g_rows_slot[p] = i % KSEL;
    g_rows_w[p]    = g_wt[i];
}

// ---------------- HMMA expert GEMM: 4-stage cp.async, 1 sync/iter -----------
// CTA tile 128x128, K-chunk 32. smem arrays stride 40 bf16 (conflict-free).
#define SROW 40
#define ARR_BYTES (128 * SROW * 2)     // 10240
#define STG_BYTES (4 * ARR_BYTES)      // 40960
#define OFF_AHI 0
#define OFF_ALO ARR_BYTES
#define OFF_BHI (2 * ARR_BYTES)
#define OFF_BLO (3 * ARR_BYTES)
#define SMEM_TOT (4 * STG_BYTES)       // 163840

template<int KDIM, int MODE>
__global__ void __launch_bounds__(256)
moe_gemm_mma() {
    constexpr int NCH  = KDIM / 32;
    constexpr int NDIM = (MODE == 1) ? N1 : H_DIM;
    const __nv_bfloat16* a_hi = (MODE == 1) ? (const __nv_bfloat16*)g_x_hi4 : (const __nv_bfloat16*)g_i_hi4;
    const __nv_bfloat16* a_lo = (MODE == 1) ? (const __nv_bfloat16*)g_x_lo4 : (const __nv_bfloat16*)g_i_lo4;
    const __nv_bfloat16* b_hi = (MODE == 1) ? (const __nv_bfloat16*)g_w1_hi4 : (const __nv_bfloat16*)g_w2_hi4;
    const __nv_bfloat16* b_lo = (MODE == 1) ? (const __nv_bfloat16*)g_w1_lo4 : (const __nv_bfloat16*)g_w2_lo4;

    const int e   = blockIdx.z;
    const int cnt = g_counts[e];
    const int m0  = blockIdx.x * 128;
    if (m0 >= cnt) return;
    const int nb  = blockIdx.y;
    const int ofs = g_ofs[e];

    extern __shared__ char smem[];
    const uint32_t sb = smem_u32(smem);

    const int tid  = threadIdx.x;
    const int wid  = tid >> 5;
    const int lane = tid & 31;
    const int wm   = wid & 1;
    const int wn   = wid >> 1;

    // ---- loader pointers: each thread owns 2 16B chunks per array ----
    const __nv_bfloat16* aH[2]; const __nv_bfloat16* aL[2];
    const __nv_bfloat16* bH[2]; const __nv_bfloat16* bL[2];
    uint32_t soff[2];
#pragma unroll
    for (int i = 0; i < 2; i++) {
        int ei = i * 256 + tid;
        int r = ei >> 2, q = ei & 3;               // r: 0..127, q: 16B chunk
        soff[i] = (uint32_t)(r * SROW * 2 + q * 16);
        int lm = m0 + r; if (lm > cnt - 1) lm = cnt - 1;
        size_t arow;
        if (MODE == 1) arow = (size_t)__ldg(&g_rows_tok[ofs + lm]) * H_DIM;
        else           arow = (size_t)(ofs + lm) * I_DIM;
        aH[i] = a_hi + arow + q * 8;
        aL[i] = a_lo + arow + q * 8;
        int gn;
        if (MODE == 1) gn = (r < 64) ? (nb * 64 + r) : (I_DIM + nb * 64 + (r - 64));
        else           gn = nb * 128 + r;
        size_t brow = ((size_t)e * NDIM + gn) * KDIM;
        bH[i] = b_hi + brow + q * 8;
        bL[i] = b_lo + brow + q * 8;
    }

    auto issue_stage = [&](int c) {
        if (c < NCH) {
            const int kt = c * 32;
            const uint32_t st = sb + (uint32_t)(c & 3) * STG_BYTES;
#pragma unroll
            for (int i = 0; i < 2; i++) {
                uint32_t d = st + soff[i];
                cpa16(d + OFF_AHI, aH[i] + kt);
                cpa16(d + OFF_ALO, aL[i] + kt);
                cpa16(d + OFF_BHI, bH[i] + kt);
                cpa16(d + OFF_BLO, bL[i] + kt);
            }
        }
        CP_COMMIT();
    };

    // ldmatrix per-thread base byte offsets within an array (proven)
    const uint32_t a_base = ((wm * 64 + (lane & 15)) * SROW + (lane >> 4) * 8) * 2;
    const uint32_t b_base = ((wn * 32 + ((lane >> 4) << 3) + (lane & 7)) * SROW + ((lane >> 3) & 1) * 8) * 2;

    float acc[4][4][4];
#pragma unroll
    for (int i = 0; i < 4; i++)
#pragma unroll
        for (int j = 0; j < 4; j++)
#pragma unroll
            for (int k = 0; k < 4; k++) acc[i][j][k] = 0.f;

    issue_stage(0); issue_stage(1); issue_stage(2);

    for (int c = 0; c < NCH; c++) {
        CP_WAIT2();            // stage c's group complete (<=2 younger pending)
        __syncthreads();       // cp.async visibility + everyone done with slot (c-1)&3
        issue_stage(c + 3);    // refill slot (c+3)&3 == (c-1)&3

        const uint32_t stg = sb + (uint32_t)(c & 3) * STG_BYTES;
#pragma unroll
        for (int kk = 0; kk < 2; kk++) {
            const uint32_t koff = kk * 32;     // 16 bf16 = 32 B
            uint32_t af[4][4], bh2[2][4], bl2[2][4];
#pragma unroll
            for (int im = 0; im < 4; im++)
                ldsm_x4(af[im], stg + OFF_AHI + a_base + im * (16 * SROW * 2) + koff);
#pragma unroll
            for (int g = 0; g < 2; g++) {
                ldsm_x4(bh2[g], stg + OFF_BHI + b_base + g * (16 * SROW * 2) + koff);
                ldsm_x4(bl2[g], stg + OFF_BLO + b_base + g * (16 * SROW * 2) + koff);
            }
#pragma unroll
            for (int im = 0; im < 4; im++)
#pragma unroll
                for (int g = 0; g < 2; g++) {
                    mma16816(acc[im][g * 2 + 0], af[im], &bh2[g][0]);
                    mma16816(acc[im][g * 2 + 1], af[im], &bh2[g][2]);
                    mma16816(acc[im][g * 2 + 0], af[im], &bl2[g][0]);
                    mma16816(acc[im][g * 2 + 1], af[im], &bl2[g][2]);
                }
#pragma unroll
            for (int im = 0; im < 4; im++)
                ldsm_x4(af[im], stg + OFF_ALO + a_base + im * (16 * SROW * 2) + koff);
#pragma unroll
            for (int im = 0; im < 4; im++)
#pragma unroll
                for (int g = 0; g < 2; g++) {
                    mma16816(acc[im][g * 2 + 0], af[im], &bh2[g][0]);
                    mma16816(acc[im][g * 2 + 1], af[im], &bh2[g][2]);
                }
        }
    }
    __syncthreads();   // all warps done reading smem before epilogue reuse

    // ---------------- epilogue ----------------
    if (MODE == 1) {
        float* Cs = (float*)smem;   // 64 KB, aliases stages (all reads done)
#pragma unroll
        for (int im = 0; im < 4; im++)
#pragma unroll
            for (int jn = 0; jn < 4; jn++) {
                int row = wm * 64 + im * 16 + (lane >> 2);
                int col = wn * 32 + jn * 8 + (lane & 3) * 2;
                *(float2*)&Cs[row * 128 + col]       = make_float2(acc[im][jn][0], acc[im][jn][1]);
                *(float2*)&Cs[(row + 8) * 128 + col] = make_float2(acc[im][jn][2], acc[im][jn][3]);
            }
        __syncthreads();
        int r = tid >> 1, half = tid & 1;
        if (m0 + r < cnt) {
            int grow = ofs + m0 + r;
            uint32_t hi16[16], lo16[16];
#pragma unroll
            for (int j = 0; j < 16; j++) {
                float g0 = Cs[r * 128 + half * 32 + 2 * j];
                float u0 = Cs[r * 128 + 64 + half * 32 + 2 * j];
                float g1 = Cs[r * 128 + half * 32 + 2 * j + 1];
                float u1 = Cs[r * 128 + 64 + half * 32 + 2 * j + 1];
                float v0 = (g0 / (1.f + __expf(-g0))) * u0;
                float v1 = (g1 / (1.f + __expf(-g1))) * u1;
                __nv_bfloat162 hh = __floats2bfloat162_rn(v0, v1);
                float2 hf = __bfloat1622float2(hh);
                __nv_bfloat162 ll = __floats2bfloat162_rn(v0 - hf.x, v1 - hf.y);
                hi16[j] = *reinterpret_cast<uint32_t*>(&hh);
                lo16[j] = *reinterpret_cast<uint32_t*>(&ll);
            }
            size_t off = ((size_t)grow * I_DIM + nb * 64 + half * 32) / 8;
#pragma unroll
            for (int j = 0; j < 4; j++) {
                g_i_hi4[off + j] = ((uint4*)hi16)[j];
                g_i_lo4[off + j] = ((uint4*)lo16)[j];
            }
        }
    } else {
#pragma unroll
        for (int im = 0; im < 4; im++) {
#pragma unroll
            for (int half = 0; half < 2; half++) {
                int r = m0 + wm * 64 + im * 16 + (lane >> 2) + half * 8;
                if (r < cnt) {
                    int gr = ofs + r;
                    float wgt = g_rows_w[gr];
                    int t = g_rows_tok[gr], sl = g_rows_slot[gr];
                    float* base = g_y + ((size_t)t * KSEL + sl) * H_DIM + nb * 128 + wn * 32;
#pragma unroll
                    for (int jn = 0; jn < 4; jn++) {
                        int col = jn * 8 + (lane & 3) * 2;
                        float2 v = make_float2(acc[im][jn][half * 2] * wgt,
                                               acc[im][jn][half * 2 + 1] * wgt);
                        *(float2*)(base + col) = v;
                    }
                }
            }
        }
    }
}

// ---------------- combine / aux ----------------
__global__ void combine_kernel(float* __restrict__ out) {
    int i = blockIdx.x * blockDim.x + threadIdx.x;
    if (i >= T_TOK * H_DIM / 4) return;
    const int nv = H_DIM / 4;
    int t = i / nv, n = i - t * nv;
    const float4* y = (const float4*)g_y;
    float4 a = y[((size_t)t * KSEL + 0) * nv + n];
    float4 b = y[((size_t)t * KSEL + 1) * nv + n];
    a.x += b.x; a.y += b.y; a.z += b.z; a.w += b.w;
    ((float4*)out)[i] = a;
}

__global__ void aux_kernel(float* __restrict__ aux_out) {
    if (threadIdx.x == 0) {
        float aux = 0.f;
        float invT = 1.f / (float)T_TOK;
        for (int e = 0; e < E_NUM; e++)
            aux += (g_prob_sum[e] * invT) * ((float)g_counts[e] * invT);
        aux_out[0] = aux * (float)E_NUM * AUX_COEF;
    }
}

// ---------------- launch ----------------
extern "C" void kernel_launch(void* const* d_in, const int* in_sizes, int n_in,
                              void* d_out, int out_size) {
    const float* x   = (const float*)d_in[0];
    const float* gw  = (const float*)d_in[1];
    const float* gup = (const float*)d_in[2];
    const float* dwn = (const float*)d_in[3];
    float* out = (float*)d_out;

    const long long need_logits = (long long)T_TOK * H_DIM + (long long)T_TOK * E_NUM;
    float* logits = ((long long)out_size >= need_logits) ? out + (size_t)T_TOK * H_DIM : nullptr;
    float* auxp   = ((long long)out_size >= need_logits + 1) ? logits + (size_t)T_TOK * E_NUM : nullptr;

    cudaFuncSetAttribute(moe_gemm_mma<H_DIM, 1>, cudaFuncAttributeMaxDynamicSharedMemorySize, SMEM_TOT);
    cudaFuncSetAttribute(moe_gemm_mma<I_DIM, 2>, cudaFuncAttributeMaxDynamicSharedMemorySize, SMEM_TOT);

    init_kernel<<<1, 32>>>();
    router_kernel<<<T_TOK, 256>>>(x, gw, logits);
    offsets_kernel<<<1, 32>>>();
    scatter_kernel<<<(ROWS_TOTAL + 255) / 256, 256>>>();

    // Pre-split fp32 -> bf16 hi/lo (x, gate_up, down); outputs selected in device code
    {
        int n4 = T_TOK * H_DIM / 4;
        split_kernel<<<(n4 + 255) / 256, 256>>>((const float4*)x, 0, n4);
        n4 = E_NUM * N1 * H_DIM / 4;
        split_kernel<<<(n4 + 255) / 256, 256>>>((const float4*)gup, 1, n4);
        n4 = E_NUM * H_DIM * I_DIM / 4;
        split_kernel<<<(n4 + 255) / 256, 256>>>((const float4*)dwn, 2, n4);
    }

    // GEMM1: (gathered x) @ gate_up^T, fused silu -> g_i_hi/g_i_lo
    moe_gemm_mma<H_DIM, 1><<<dim3(32, I_DIM / 64, E_NUM), 256, SMEM_TOT>>>();
    // GEMM2: inter @ down^T, scaled, scattered -> g_y
    moe_gemm_mma<I_DIM, 2><<<dim3(32, H_DIM / 128, E_NUM), 256, SMEM_TOT>>>();

    combine_kernel<<<(T_TOK * H_DIM / 4 + 255) / 256, 256>>>(out);
    if (auxp) aux_kernel<<<1, 32>>>(auxp);
}

// round 8
// speedup vs baseline: 1.2256x; 1.1016x over previous
#include <cuda_runtime.h>
#include <cuda_bf16.h>
#include <math.h>
#include <stdint.h>

// Problem constants
#define T_TOK 4096
#define H_DIM 2048
#define E_NUM 8
#define I_DIM 768
#define KSEL  2
#define N1    (2*I_DIM)
#define ROWS_TOTAL (T_TOK*KSEL)
#define AUX_COEF 0.001f

// ---------------- scratch (device-code access ONLY — never host args) -------
__device__ uint4 g_x_hi4[(size_t)T_TOK * H_DIM / 8];
__device__ uint4 g_x_lo4[(size_t)T_TOK * H_DIM / 8];
__device__ uint4 g_w1_hi4[(size_t)E_NUM * N1 * H_DIM / 8];
__device__ uint4 g_w1_lo4[(size_t)E_NUM * N1 * H_DIM / 8];
__device__ uint4 g_w2_hi4[(size_t)E_NUM * H_DIM * I_DIM / 8];
__device__ uint4 g_w2_lo4[(size_t)E_NUM * H_DIM * I_DIM / 8];
__device__ uint4 g_i_hi4[(size_t)ROWS_TOTAL * I_DIM / 8];
__device__ uint4 g_i_lo4[(size_t)ROWS_TOTAL * I_DIM / 8];
__device__ float g_y[(size_t)ROWS_TOTAL * H_DIM];
__device__ int   g_sel[ROWS_TOTAL];
__device__ float g_wt[ROWS_TOTAL];
__device__ int   g_counts[E_NUM];
__device__ int   g_ofs[E_NUM];
__device__ int   g_cursor[E_NUM];
__device__ int   g_rows_tok[ROWS_TOTAL];
__device__ int   g_rows_slot[ROWS_TOTAL];
__device__ float g_rows_w[ROWS_TOTAL];
__device__ float g_prob_sum[E_NUM];

// ---------------- helpers ----------------
__device__ __forceinline__ uint32_t smem_u32(const void* p) {
    uint32_t a;
    asm("{ .reg .u64 t; cvta.to.shared.u64 t, %1; cvt.u32.u64 %0, t; }" : "=r"(a) : "l"(p));
    return a;
}
__device__ __forceinline__ void ldsm_x4(uint32_t* r, uint32_t addr) {
    asm volatile("ldmatrix.sync.aligned.m8n8.x4.shared.b16 {%0,%1,%2,%3}, [%4];"
        : "=r"(r[0]), "=r"(r[1]), "=r"(r[2]), "=r"(r[3]) : "r"(addr));
}
__device__ __forceinline__ void mma16816(float* c, const uint32_t* a, const uint32_t* b) {
    asm volatile("mma.sync.aligned.m16n8k16.row.col.f32.bf16.bf16.f32 "
        "{%0,%1,%2,%3}, {%4,%5,%6,%7}, {%8,%9}, {%0,%1,%2,%3};"
        : "+f"(c[0]), "+f"(c[1]), "+f"(c[2]), "+f"(c[3])
        : "r"(a[0]), "r"(a[1]), "r"(a[2]), "r"(a[3]), "r"(b[0]), "r"(b[1]));
}
__device__ __forceinline__ void cpa16(uint32_t dst, const void* src) {
    asm volatile("cp.async.cg.shared.global [%0], [%1], 16;" :: "r"(dst), "l"(src) : "memory");
}
#define CP_COMMIT() asm volatile("cp.async.commit_group;" ::: "memory")
#define CP_WAIT1()  asm volatile("cp.async.wait_group 1;" ::: "memory")

__device__ __forceinline__ void split4(float4 v, uint2& h, uint2& l) {
    __nv_bfloat162 hxy = __floats2bfloat162_rn(v.x, v.y);
    __nv_bfloat162 hzw = __floats2bfloat162_rn(v.z, v.w);
    float2 fxy = __bfloat1622float2(hxy);
    float2 fzw = __bfloat1622float2(hzw);
    __nv_bfloat162 lxy = __floats2bfloat162_rn(v.x - fxy.x, v.y - fxy.y);
    __nv_bfloat162 lzw = __floats2bfloat162_rn(v.z - fzw.x, v.w - fzw.y);
    h.x = *reinterpret_cast<uint32_t*>(&hxy); h.y = *reinterpret_cast<uint32_t*>(&hzw);
    l.x = *reinterpret_cast<uint32_t*>(&lxy); l.y = *reinterpret_cast<uint32_t*>(&lzw);
}

// ---------------- split precompute (globals selected in DEVICE code) --------
__global__ void split_kernel(const float4* __restrict__ in, int which, int n4) {
    int i = blockIdx.x * blockDim.x + threadIdx.x;
    if (i >= n4) return;
    uint2* hi; uint2* lo;
    if (which == 0)      { hi = (uint2*)g_x_hi4;  lo = (uint2*)g_x_lo4;  }
    else if (which == 1) { hi = (uint2*)g_w1_hi4; lo = (uint2*)g_w1_lo4; }
    else                 { hi = (uint2*)g_w2_hi4; lo = (uint2*)g_w2_lo4; }
    uint2 h, l;
    split4(in[i], h, l);
    hi[i] = h; lo[i] = l;
}

// ---------------- init / router / offsets / scatter (validated) ------------
__global__ void init_kernel() {
    int i = threadIdx.x;
    if (i < E_NUM) { g_counts[i] = 0; g_prob_sum[i] = 0.f; }
}

__global__ void router_kernel(const float* __restrict__ x,
                              const float* __restrict__ gw,
                              float* __restrict__ logits_out) {
    const int t = blockIdx.x;
    const float* xr = x + (size_t)t * H_DIM;
    float acc[E_NUM];
#pragma unroll
    for (int e = 0; e < E_NUM; e++) acc[e] = 0.f;
    for (int h = threadIdx.x; h < H_DIM; h += blockDim.x) {
        float xv = xr[h];
        const float4 g0 = *(const float4*)(gw + (size_t)h * E_NUM);
        const float4 g1 = *(const float4*)(gw + (size_t)h * E_NUM + 4);
        acc[0] += xv * g0.x; acc[1] += xv * g0.y; acc[2] += xv * g0.z; acc[3] += xv * g0.w;
        acc[4] += xv * g1.x; acc[5] += xv * g1.y; acc[6] += xv * g1.z; acc[7] += xv * g1.w;
    }
#pragma unroll
    for (int e = 0; e < E_NUM; e++)
#pragma unroll
        for (int o = 16; o; o >>= 1) acc[e] += __shfl_xor_sync(0xffffffffu, acc[e], o);
    __shared__ float red[E_NUM][8];
    int warp = threadIdx.x >> 5, lane = threadIdx.x & 31;
    if (lane == 0)
#pragma unroll
        for (int e = 0; e < E_NUM; e++) red[e][warp] = acc[e];
    __syncthreads();
    if (threadIdx.x == 0) {
        float lg[E_NUM];
#pragma unroll
        for (int e = 0; e < E_NUM; e++) {
            float s = 0.f;
#pragma unroll
            for (int w = 0; w < 8; w++) s += red[e][w];
            lg[e] = s;
        }
        if (logits_out)
#pragma unroll
            for (int e = 0; e < E_NUM; e++) logits_out[(size_t)t * E_NUM + e] = lg[e];
        float mx = lg[0];
#pragma unroll
        for (int e = 1; e < E_NUM; e++) mx = fmaxf(mx, lg[e]);
        float p[E_NUM], s = 0.f;
#pragma unroll
        for (int e = 0; e < E_NUM; e++) { p[e] = expf(lg[e] - mx); s += p[e]; }
        float inv = 1.f / s;
#pragma unroll
        for (int e = 0; e < E_NUM; e++) { p[e] *= inv; atomicAdd(&g_prob_sum[e], p[e]); }
        bool used[E_NUM];
#pragma unroll
        for (int e = 0; e < E_NUM; e++) used[e] = false;
        int si[KSEL]; float sp[KSEL]; float wsum = 0.f;
#pragma unroll
        for (int k = 0; k < KSEL; k++) {
            int bi = -1; float bv = -1.f;
#pragma unroll
            for (int e = 0; e < E_NUM; e++)
                if (!used[e] && p[e] > bv) { bv = p[e]; bi = e; }
            used[bi] = true; si[k] = bi; sp[k] = bv; wsum += bv;
        }
        float winv = 1.f / wsum;
#pragma unroll
        for (int k = 0; k < KSEL; k++) {
            g_sel[t * KSEL + k] = si[k];
            g_wt[t * KSEL + k]  = sp[k] * winv;
            atomicAdd(&g_counts[si[k]], 1);
        }
    }
}

__global__ void offsets_kernel() {
    if (threadIdx.x == 0) {
        int run = 0;
        for (int e = 0; e < E_NUM; e++) { g_ofs[e] = run; g_cursor[e] = run; run += g_counts[e]; }
    }
}

__global__ void scatter_kernel() {
    int i = blockIdx.x * blockDim.x + threadIdx.x;
    if (i >= ROWS_TOTAL) return;
    int e = g_sel[i];
    int p = atomicAdd(&g_cursor[e], 1);
    g_rows_tok[p]  = i / KSEL;
    g_rows_slot[p] = i % KSEL;
    g_rows_w[p]    = g_wt[i];
}

// ---------------- HMMA expert GEMM: 2-stage cp.async, 2 CTAs/SM -------------
// CTA tile 128x128, K-chunk 32. smem stride 40 bf16 (proven conflict-free).
#define SROW 40
#define ARR_BYTES (128 * SROW * 2)     // 10240
#define STG_BYTES (4 * ARR_BYTES)      // 40960
#define OFF_AHI 0
#define OFF_ALO ARR_BYTES
#define OFF_BHI (2 * ARR_BYTES)
#define OFF_BLO (3 * ARR_BYTES)
#define SMEM_TOT (2 * STG_BYTES)       // 81920 -> 2 CTAs/SM

template<int KDIM, int MODE>
__global__ void __launch_bounds__(256, 2)
moe_gemm_mma() {
    constexpr int NCH  = KDIM / 32;
    constexpr int NDIM = (MODE == 1) ? N1 : H_DIM;
    const __nv_bfloat16* a_hi = (MODE == 1) ? (const __nv_bfloat16*)g_x_hi4 : (const __nv_bfloat16*)g_i_hi4;
    const __nv_bfloat16* a_lo = (MODE == 1) ? (const __nv_bfloat16*)g_x_lo4 : (const __nv_bfloat16*)g_i_lo4;
    const __nv_bfloat16* b_hi = (MODE == 1) ? (const __nv_bfloat16*)g_w1_hi4 : (const __nv_bfloat16*)g_w2_hi4;
    const __nv_bfloat16* b_lo = (MODE == 1) ? (const __nv_bfloat16*)g_w1_lo4 : (const __nv_bfloat16*)g_w2_lo4;

    const int e   = blockIdx.z;
    const int cnt = g_counts[e];
    const int m0  = blockIdx.x * 128;
    if (m0 >= cnt) return;
    const int nb  = blockIdx.y;
    const int ofs = g_ofs[e];

    extern __shared__ char smem[];
    const uint32_t sb = smem_u32(smem);

    const int tid  = threadIdx.x;
    const int wid  = tid >> 5;
    const int lane = tid & 31;
    const int wm   = wid & 1;
    const int wn   = wid >> 1;

    // ---- loader state: row offsets (element index), not pointers (regs) ----
    size_t arow[2], brow[2];
    uint32_t soff[2];
#pragma unroll
    for (int i = 0; i < 2; i++) {
        int ei = i * 256 + tid;
        int r = ei >> 2, q = ei & 3;               // r: 0..127, q: 16B chunk
        soff[i] = (uint32_t)(r * SROW * 2 + q * 16);
        int lm = m0 + r; if (lm > cnt - 1) lm = cnt - 1;
        if (MODE == 1) arow[i] = (size_t)__ldg(&g_rows_tok[ofs + lm]) * H_DIM + q * 8;
        else           arow[i] = (size_t)(ofs + lm) * I_DIM + q * 8;
        int gn;
        if (MODE == 1) gn = (r < 64) ? (nb * 64 + r) : (I_DIM + nb * 64 + (r - 64));
        else           gn = nb * 128 + r;
        brow[i] = ((size_t)e * NDIM + gn) * KDIM + q * 8;
    }

    auto issue_stage = [&](int c) {
        if (c < NCH) {
            const int kt = c * 32;
            const uint32_t st = sb + (uint32_t)(c & 1) * STG_BYTES;
#pragma unroll
            for (int i = 0; i < 2; i++) {
                uint32_t d = st + soff[i];
                cpa16(d + OFF_AHI, a_hi + arow[i] + kt);
                cpa16(d + OFF_ALO, a_lo + arow[i] + kt);
                cpa16(d + OFF_BHI, b_hi + brow[i] + kt);
                cpa16(d + OFF_BLO, b_lo + brow[i] + kt);
            }
        }
        CP_COMMIT();
    };

    // ldmatrix per-thread base byte offsets within an array (proven)
    const uint32_t a_base = ((wm * 64 + (lane & 15)) * SROW + (lane >> 4) * 8) * 2;
    const uint32_t b_base = ((wn * 32 + ((lane >> 4) << 3) + (lane & 7)) * SROW + ((lane >> 3) & 1) * 8) * 2;

    float acc[4][4][4];
#pragma unroll
    for (int i = 0; i < 4; i++)
#pragma unroll
        for (int j = 0; j < 4; j++)
#pragma unroll
            for (int k = 0; k < 4; k++) acc[i][j][k] = 0.f;

    issue_stage(0); issue_stage(1);

    for (int c = 0; c < NCH; c++) {
        CP_WAIT1();            // stage c complete (<=1 younger group pending)
        __syncthreads();

        const uint32_t stg = sb + (uint32_t)(c & 1) * STG_BYTES;
#pragma unroll
        for (int kk = 0; kk < 2; kk++) {
            const uint32_t koff = kk * 32;     // 16 bf16 = 32 B
            uint32_t af[4][4], bh2[2][4], bl2[2][4];
#pragma unroll
            for (int im = 0; im < 4; im++)
                ldsm_x4(af[im], stg + OFF_AHI + a_base + im * (16 * SROW * 2) + koff);
#pragma unroll
            for (int g = 0; g < 2; g++) {
                ldsm_x4(bh2[g], stg + OFF_BHI + b_base + g * (16 * SROW * 2) + koff);
                ldsm_x4(bl2[g], stg + OFF_BLO + b_base + g * (16 * SROW * 2) + koff);
            }
            // pass 1: all hi*Bhi (16 distinct accumulators)
#pragma unroll
            for (int im = 0; im < 4; im++)
#pragma unroll
                for (int g = 0; g < 2; g++) {
                    mma16816(acc[im][g * 2 + 0], af[im], &bh2[g][0]);
                    mma16816(acc[im][g * 2 + 1], af[im], &bh2[g][2]);
                }
            // pass 2: all hi*Blo (same accs, distance 16)
#pragma unroll
            for (int im = 0; im < 4; im++)
#pragma unroll
                for (int g = 0; g < 2; g++) {
                    mma16816(acc[im][g * 2 + 0], af[im], &bl2[g][0]);
                    mma16816(acc[im][g * 2 + 1], af[im], &bl2[g][2]);
                }
            // pass 3: all lo*Bhi
#pragma unroll
            for (int im = 0; im < 4; im++)
                ldsm_x4(af[im], stg + OFF_ALO + a_base + im * (16 * SROW * 2) + koff);
#pragma unroll
            for (int im = 0; im < 4; im++)
#pragma unroll
                for (int g = 0; g < 2; g++) {
                    mma16816(acc[im][g * 2 + 0], af[im], &bh2[g][0]);
                    mma16816(acc[im][g * 2 + 1], af[im], &bh2[g][2]);
                }
        }
        __syncthreads();       // all warps done with slot c&1
        issue_stage(c + 2);    // refill it
    }

    // ---------------- epilogue ----------------
    if (MODE == 1) {
        float* Cs = (float*)smem;   // 64 KB, aliases stages (all reads done)
#pragma unroll
        for (int im = 0; im < 4; im++)
#pragma unroll
            for (int jn = 0; jn < 4; jn++) {
                int row = wm * 64 + im * 16 + (lane >> 2);
                int col = wn * 32 + jn * 8 + (lane & 3) * 2;
                *(float2*)&Cs[row * 128 + col]       = make_float2(acc[im][jn][0], acc[im][jn][1]);
                *(float2*)&Cs[(row + 8) * 128 + col] = make_float2(acc[im][jn][2], acc[im][jn][3]);
            }
        __syncthreads();
        int r = tid >> 1, half = tid & 1;
        if (m0 + r < cnt) {
            int grow = ofs + m0 + r;
            uint32_t hi16[16], lo16[16];
#pragma unroll
            for (int j = 0; j < 16; j++) {
                float g0 = Cs[r * 128 + half * 32 + 2 * j];
                float u0 = Cs[r * 128 + 64 + half * 32 + 2 * j];
                float g1 = Cs[r * 128 + half * 32 + 2 * j + 1];
                float u1 = Cs[r * 128 + 64 + half * 32 + 2 * j + 1];
                float v0 = (g0 / (1.f + __expf(-g0))) * u0;
                float v1 = (g1 / (1.f + __expf(-g1))) * u1;
                __nv_bfloat162 hh = __floats2bfloat162_rn(v0, v1);
                float2 hf = __bfloat1622float2(hh);
                __nv_bfloat162 ll = __floats2bfloat162_rn(v0 - hf.x, v1 - hf.y);
                hi16[j] = *reinterpret_cast<uint32_t*>(&hh);
                lo16[j] = *reinterpret_cast<uint32_t*>(&ll);
            }
            size_t off = ((size_t)grow * I_DIM + nb * 64 + half * 32) / 8;
#pragma unroll
            for (int j = 0; j < 4; j++) {
                g_i_hi4[off + j] = ((uint4*)hi16)[j];
                g_i_lo4[off + j] = ((uint4*)lo16)[j];
            }
        }
    } else {
#pragma unroll
        for (int im = 0; im < 4; im++) {
#pragma unroll
            for (int half = 0; half < 2; half++) {
                int r = m0 + wm * 64 + im * 16 + (lane >> 2) + half * 8;
                if (r < cnt) {
                    int gr = ofs + r;
                    float wgt = g_rows_w[gr];
                    int t = g_rows_tok[gr], sl = g_rows_slot[gr];
                    float* base = g_y + ((size_t)t * KSEL + sl) * H_DIM + nb * 128 + wn * 32;
#pragma unroll
                    for (int jn = 0; jn < 4; jn++) {
                        int col = jn * 8 + (lane & 3) * 2;
                        float2 v = make_float2(acc[im][jn][half * 2] * wgt,
                                               acc[im][jn][half * 2 + 1] * wgt);
                        *(float2*)(base + col) = v;
                    }
                }
            }
        }
    }
}

// ---------------- combine / aux ----------------
__global__ void combine_kernel(float* __restrict__ out) {
    int i = blockIdx.x * blockDim.x + threadIdx.x;
    if (i >= T_TOK * H_DIM / 4) return;
    const int nv = H_DIM / 4;
    int t = i / nv, n = i - t * nv;
    const float4* y = (const float4*)g_y;
    float4 a = y[((size_t)t * KSEL + 0) * nv + n];
    float4 b = y[((size_t)t * KSEL + 1) * nv + n];
    a.x += b.x; a.y += b.y; a.z += b.z; a.w += b.w;
    ((float4*)out)[i] = a;
}

__global__ void aux_kernel(float* __restrict__ aux_out) {
    if (threadIdx.x == 0) {
        float aux = 0.f;
        float invT = 1.f / (float)T_TOK;
        for (int e = 0; e < E_NUM; e++)
            aux += (g_prob_sum[e] * invT) * ((float)g_counts[e] * invT);
        aux_out[0] = aux * (float)E_NUM * AUX_COEF;
    }
}

// ---------------- launch ----------------
extern "C" void kernel_launch(void* const* d_in, const int* in_sizes, int n_in,
                              void* d_out, int out_size) {
    const float* x   = (const float*)d_in[0];
    const float* gw  = (const float*)d_in[1];
    const float* gup = (const float*)d_in[2];
    const float* dwn = (const float*)d_in[3];
    float* out = (float*)d_out;

    const long long need_logits = (long long)T_TOK * H_DIM + (long long)T_TOK * E_NUM;
    float* logits = ((long long)out_size >= need_logits) ? out + (size_t)T_TOK * H_DIM : nullptr;
    float* auxp   = ((long long)out_size >= need_logits + 1) ? logits + (size_t)T_TOK * E_NUM : nullptr;

    cudaFuncSetAttribute(moe_gemm_mma<H_DIM, 1>, cudaFuncAttributeMaxDynamicSharedMemorySize, SMEM_TOT);
    cudaFuncSetAttribute(moe_gemm_mma<I_DIM, 2>, cudaFuncAttributeMaxDynamicSharedMemorySize, SMEM_TOT);

    init_kernel<<<1, 32>>>();
    router_kernel<<<T_TOK, 256>>>(x, gw, logits);
    offsets_kernel<<<1, 32>>>();
    scatter_kernel<<<(ROWS_TOTAL + 255) / 256, 256>>>();

    // Pre-split fp32 -> bf16 hi/lo (x, gate_up, down); outputs selected in device code
    {
        int n4 = T_TOK * H_DIM / 4;
        split_kernel<<<(n4 + 255) / 256, 256>>>((const float4*)x, 0, n4);
        n4 = E_NUM * N1 * H_DIM / 4;
        split_kernel<<<(n4 + 255) / 256, 256>>>((const float4*)gup, 1, n4);
        n4 = E_NUM * H_DIM * I_DIM / 4;
        split_kernel<<<(n4 + 255) / 256, 256>>>((const float4*)dwn, 2, n4);
    }

    // GEMM1: (gathered x) @ gate_up^T, fused silu -> g_i_hi/g_i_lo
    moe_gemm_mma<H_DIM, 1><<<dim3(32, I_DIM / 64, E_NUM), 256, SMEM_TOT>>>();
    // GEMM2: inter @ down^T, scaled, scattered -> g_y
    moe_gemm_mma<I_DIM, 2><<<dim3(32, H_DIM / 128, E_NUM), 256, SMEM_TOT>>>();

    combine_kernel<<<(T_TOK * H_DIM / 4 + 255) / 256, 256>>>(out);
    if (auxp) aux_kernel<<<1, 32>>>(auxp);
}